// round 13
// baseline (speedup 1.0000x reference)
#include <cuda_runtime.h>
#include <cuda_fp16.h>
#include <cstdint>

#define Bn 8192
#define En 16
#define Zn 256
#define Hn 1024
#define Un 256
#define TM 64
#define MAXT 144
#define NT 512
#define NTPRE 512
#define NCG 128                  // N chunk per group (per gemm call)
#define KC 64                    // K chunk
#define LDA 264                  // A smem row stride (halves)
#define LDB 72                   // B smem row stride (halves)
#define BPART (NCG*LDB*2)        // 18432 B per buffer

// smem byte offsets
#define OAZ 0                    // z tile   (64 x LDA halves)
#define OA2 33792                // a tile
#define OAU 67584                // u tile
#define OBS 101376               // B rings: group g at OBS + g*3*BPART
#define SMEM_DYN (OBS + 6*BPART) // 211968 (207KB)

// ---------------- device scratch ----------------
__device__ int g_perm[Bn];
__device__ int g_te[MAXT], g_ts[MAXT], g_tr[MAXT];
__device__ int g_ntiles;
__device__ __half g_Wzh[(size_t)En*Zn*Zn];
__device__ __half g_Whh[(size_t)En*Hn*Zn];
__device__ __half g_Wuh[(size_t)En*Un*Un];
__device__ __half g_zh[(size_t)Bn*Zn];
__device__ __half g_uh[(size_t)Bn*Un];

// ---------------- helpers ----------------
__device__ __forceinline__ uint32_t s2u(const void* p) {
    uint32_t a;
    asm("{ .reg .u64 t; cvta.to.shared.u64 t, %1; cvt.u32.u64 %0, t; }" : "=r"(a) : "l"(p));
    return a;
}
__device__ __forceinline__ void cpa16(uint32_t dst, const void* src) {
    asm volatile("cp.async.ca.shared.global [%0], [%1], 16;" :: "r"(dst), "l"(src));
}
__device__ __forceinline__ void cpa16z(uint32_t dst, const void* src, uint32_t sz) {
    asm volatile("cp.async.ca.shared.global [%0], [%1], 16, %2;" :: "r"(dst), "l"(src), "r"(sz));
}
__device__ __forceinline__ void cpa_commit() { asm volatile("cp.async.commit_group;" ::: "memory"); }
template<int N> __device__ __forceinline__ void cpa_wait() {
    asm volatile("cp.async.wait_group %0;" :: "n"(N) : "memory");
}
__device__ __forceinline__ void gbar(int id) {
    asm volatile("bar.sync %0, 256;" :: "r"(id) : "memory");
}
__device__ __forceinline__ void ldm4(uint32_t r[4], uint32_t addr) {
    asm volatile("ldmatrix.sync.aligned.m8n8.x4.shared.b16 {%0,%1,%2,%3}, [%4];"
                 : "=r"(r[0]), "=r"(r[1]), "=r"(r[2]), "=r"(r[3]) : "r"(addr));
}
__device__ __forceinline__ void mma16816(float c[4], const uint32_t a[4], uint32_t b0, uint32_t b1) {
    asm volatile("mma.sync.aligned.m16n8k16.row.col.f32.f16.f16.f32 "
                 "{%0,%1,%2,%3}, {%4,%5,%6,%7}, {%8,%9}, {%0,%1,%2,%3};"
                 : "+f"(c[0]), "+f"(c[1]), "+f"(c[2]), "+f"(c[3])
                 : "r"(a[0]), "r"(a[1]), "r"(a[2]), "r"(a[3]), "r"(b0), "r"(b1));
}

// ---------------- fused pre-pass: cvt (weights + z + u) + setup ----------------
#define NWz4 (En*Zn*Zn/4)        // 262144
#define NWh4 (En*Hn*Zn/4)        // 1048576
#define NWu4 (En*Un*Un/4)        // 262144
#define Nz4  (Bn*Zn/4)           // 524288
#define Nu4  (Bn*Un/4)           // 524288
#define NCVT (NWz4+NWh4+NWu4+Nz4+Nu4)   // 2621440
#define PREBLK (NCVT/(NTPRE*2))          // 2560

__device__ __forceinline__ void cvt_one(int j, const float* __restrict__ Wz,
                                        const float* __restrict__ Wh,
                                        const float* __restrict__ Wu,
                                        const float* __restrict__ z,
                                        const float* __restrict__ u) {
    const float* src; __half* dh;
    if (j < NWz4)                { src = Wz; dh = g_Wzh; }
    else if ((j -= NWz4) < NWh4) { src = Wh; dh = g_Whh; }
    else if ((j -= NWh4) < NWu4) { src = Wu; dh = g_Wuh; }
    else if ((j -= NWu4) < Nz4)  { src = z;  dh = g_zh; }
    else { j -= Nz4;               src = u;  dh = g_uh; }
    float4 v = __ldg((const float4*)src + j);
    union { __half2 h[2]; uint2 q; } P;
    P.h[0] = __floats2half2_rn(v.x, v.y);
    P.h[1] = __floats2half2_rn(v.z, v.w);
    ((uint2*)dh)[j] = P.q;
}

__global__ __launch_bounds__(NTPRE) void k_pre(const int* __restrict__ rng,
                                               const float* __restrict__ Wz,
                                               const float* __restrict__ Wh,
                                               const float* __restrict__ Wu,
                                               const float* __restrict__ z,
                                               const float* __restrict__ u) {
    if (blockIdx.x == PREBLK) {
        // ---- setup block: smem-cached rng -> hist/scan/scatter ----
        __shared__ int srng[Bn];          // 32KB
        __shared__ int sc[En], soff[En], scur[En];
        const int tid = threadIdx.x, lane = tid & 31;
        for (int i = tid; i < Bn; i += NTPRE) srng[i] = rng[i];
        if (tid < En) { sc[tid] = 0; scur[tid] = 0; }
        __syncthreads();
        for (int i = tid; i < Bn; i += NTPRE) {
            int e = srng[i];
            unsigned m = __match_any_sync(0xffffffffu, e);
            if (lane == __ffs(m) - 1) atomicAdd(&sc[e], __popc(m));
        }
        __syncthreads();
        if (tid == 0) {
            int acc = 0, nt = 0;
            for (int e = 0; e < En; e++) {
                soff[e] = acc;
                int c = sc[e];
                for (int s = 0; s < c; s += TM) {
                    g_te[nt] = e;
                    g_ts[nt] = acc + s;
                    g_tr[nt] = (c - s) < TM ? (c - s) : TM;
                    nt++;
                }
                acc += c;
            }
            g_ntiles = nt;
        }
        __syncthreads();
        for (int i = tid; i < Bn; i += NTPRE) {
            int e = srng[i];
            unsigned m = __match_any_sync(0xffffffffu, e);
            int leader = __ffs(m) - 1;
            int rank = __popc(m & ((1u << lane) - 1u));
            int base = 0;
            if (lane == leader) base = atomicAdd(&scur[e], __popc(m));
            base = __shfl_sync(0xffffffffu, base, leader);
            g_perm[soff[e] + base + rank] = i;
        }
        return;
    }
    const int i0 = blockIdx.x * (NTPRE * 2) + threadIdx.x;
    cvt_one(i0, Wz, Wh, Wu, z, u);
    cvt_one(i0 + NTPRE, Wz, Wh, Wu, z, u);
}

// ---------------- A staging: gathered fp16 rows via cp.async (all 512 thr) ----------------
__device__ __forceinline__ void stage_af16(char* smc, int off, const __half* __restrict__ g,
                                           const int* ss, int tid) {
#pragma unroll
    for (int i = tid; i < TM * 32; i += NT) {
        int r = i >> 5, c = (i & 31) << 3;
        int s = ss[r];
        cpa16z(s2u(smc + off + (uint32_t)(r * LDA + c) * 2),
               g + (size_t)(s >= 0 ? s : 0) * 256 + c, (s >= 0) ? 16u : 0u);
    }
}

// B chunk: 128 rows x 64 halves via cp.async, staged by ONE group (256 threads)
__device__ __forceinline__ void stage_b(uint32_t bh, const __half* __restrict__ gh,
                                        int kc, int tidg) {
#pragma unroll
    for (int i = tidg; i < NCG * 8; i += 256) {
        int r = i >> 3, c = (i & 7) << 3;
        cpa16(bh + (uint32_t)(r * LDB + c) * 2, gh + (size_t)r * 256 + kc * KC + c);
    }
}

// ---------------- group GEMM: one 64x128 output chunk ----------------
// PRESTAGED: caller already staged+committed chunk 0 into buffer rot%3.
template<bool PRESTAGED>
__device__ __forceinline__ void gemm_nc(uint32_t aB, uint32_t obsg, int rot, int gid,
                                        const __half* __restrict__ gB,
                                        float c[2][4][4], int tidg) {
    const int lane = tidg & 31, wig = tidg >> 5;
    const int wm = wig >> 2, wn = wig & 3;
    const int lrow = (lane & 7) + ((lane >> 3) & 1) * 8;
    const int lk8  = (lane >> 4) * 8;

#pragma unroll
    for (int mt = 0; mt < 2; mt++)
#pragma unroll
        for (int nt = 0; nt < 4; nt++)
#pragma unroll
            for (int j = 0; j < 4; j++) c[mt][nt][j] = 0.f;

    if (!PRESTAGED) {
        stage_b(obsg + (uint32_t)(rot % 3) * BPART, gB, 0, tidg);
        cpa_commit();
    }

#pragma unroll
    for (int kc = 0; kc < 4; kc++) {
        if (kc < 3) {
            stage_b(obsg + (uint32_t)((rot + kc + 1) % 3) * BPART, gB, kc + 1, tidg);
            cpa_commit();
            cpa_wait<1>();
        } else {
            cpa_wait<0>();
        }
        gbar(1 + gid);

        const uint32_t bH = obsg + (uint32_t)((rot + kc) % 3) * BPART;
#pragma unroll
        for (int k16 = 0; k16 < 4; k16++) {
            const int ka = kc * KC + k16 * 16 + lk8;
            uint32_t ah[2][4];
#pragma unroll
            for (int mt = 0; mt < 2; mt++)
                ldm4(ah[mt], aB + (uint32_t)((wm * 32 + mt * 16 + lrow) * LDA + ka) * 2);
            uint32_t bf[2][4];
#pragma unroll
            for (int ng = 0; ng < 2; ng++)
                ldm4(bf[ng], bH + (uint32_t)((wn * 32 + ng * 16 + lrow) * LDB + k16 * 16 + lk8) * 2);
#pragma unroll
            for (int mt = 0; mt < 2; mt++)
#pragma unroll
                for (int nt = 0; nt < 4; nt++)
                    mma16816(c[mt][nt], ah[mt], bf[nt >> 1][nt & 1], bf[nt >> 1][(nt & 1) + 2]);
        }
    }
}

// ---------------- fused MoE kernel (2 independent 8-warp groups per CTA) ----------------
__global__ __launch_bounds__(NT, 1)
void k_moe(const float* __restrict__ bz, const float* __restrict__ bhb,
           float* __restrict__ out) {
    const int bt = blockIdx.x;
    if (bt >= g_ntiles) return;
    const int e = g_te[bt], start = g_ts[bt], rows = g_tr[bt];
    const int tid = threadIdx.x;
    const int gid = tid >> 8;
    const int tidg = tid & 255;
    const int lane = tid & 31, wig = tidg >> 5;
    const int wm = wig >> 2, wn = wig & 3;
    const int t4 = lane >> 2, t2 = (lane & 3) * 2;

    extern __shared__ char smc[];
    const uint32_t sm0 = s2u(smc);
    const uint32_t aZ = sm0 + OAZ, a2 = sm0 + OA2, aU = sm0 + OAU;
    const uint32_t obsg = sm0 + OBS + (uint32_t)gid * 3 * BPART;

    __shared__ int ss[TM];
    if (tid < TM) ss[tid] = (tid < rows) ? g_perm[start + tid] : -1;
    __syncthreads();

    const __half* Wze = g_Wzh + (size_t)e * Zn * Zn;
    const __half* Whe = g_Whh + (size_t)e * Hn * Zn;
    const __half* Wue = g_Wuh + (size_t)e * Un * Un;

    // ---- prologue: async-stage z AND u tiles (one group), then GEMM1 B chunk0 ----
    stage_af16(smc, OAZ, g_zh, ss, tid);
    stage_af16(smc, OAU, g_uh, ss, tid);
    cpa_commit();                                  // group: z+u tiles
    stage_b(obsg, Wze + (size_t)(gid * NCG) * Zn, 0, tidg);
    cpa_commit();                                  // group: GEMM1 chunk0
    cpa_wait<1>();                                 // z+u arrived (chunk0 may fly)
    __syncthreads();                               // z/u visible CTA-wide

    float c[2][4][4];
    int rot = 0;

    // ---- GEMM1: a = z @ Wz^T + bz -> a2 (fp16); group N-half; chunk0 prestaged ----
    {
        const int n0 = gid * NCG;
        gemm_nc<true>(aZ, obsg, rot, gid, Wze + (size_t)n0 * Zn, c, tidg); rot++;
        const float* bzp = bz + (size_t)e * Zn + n0;
#pragma unroll
        for (int mt = 0; mt < 2; mt++) {
            const int r0 = wm * 32 + mt * 16 + t4;
#pragma unroll
            for (int nt = 0; nt < 4; nt++) {
                const int col = wn * 32 + nt * 8 + t2;
                const float2 bb = *(const float2*)(bzp + col);
                uint32_t o = (uint32_t)(r0 * LDA + n0 + col) * 2;
                *(__half2*)(smc + OA2 + o) = __floats2half2_rn(c[mt][nt][0] + bb.x, c[mt][nt][1] + bb.y);
                o = (uint32_t)((r0 + 8) * LDA + n0 + col) * 2;
                *(__half2*)(smc + OA2 + o) = __floats2half2_rn(c[mt][nt][2] + bb.x, c[mt][nt][3] + bb.y);
            }
        }
    }
    __syncthreads();                               // a2 complete (both halves)

    // ---- GEMM2: h = relu(a @ Wh^T + bh) -> out; groups drift freely ----
    {
        for (int nc = 0; nc < 4; nc++) {
            const int n0 = nc * 256 + gid * NCG;
            gemm_nc<false>(a2, obsg, rot, gid, Whe + (size_t)n0 * Zn, c, tidg); rot++;
            const float* bhp = bhb + (size_t)e * Hn + n0;
#pragma unroll
            for (int mt = 0; mt < 2; mt++) {
                const int r0 = wm * 32 + mt * 16 + t4;
                const int s0 = ss[r0], s1 = ss[r0 + 8];
#pragma unroll
                for (int nt = 0; nt < 4; nt++) {
                    const int col = wn * 32 + nt * 8 + t2;
                    const float2 bb = *(const float2*)(bhp + col);
                    if (s0 >= 0) {
                        float2 o;
                        o.x = fmaxf(c[mt][nt][0] + bb.x, 0.f);
                        o.y = fmaxf(c[mt][nt][1] + bb.y, 0.f);
                        *(float2*)(out + (size_t)s0 * Hn + n0 + col) = o;
                    }
                    if (s1 >= 0) {
                        float2 o;
                        o.x = fmaxf(c[mt][nt][2] + bb.x, 0.f);
                        o.y = fmaxf(c[mt][nt][3] + bb.y, 0.f);
                        *(float2*)(out + (size_t)s1 * Hn + n0 + col) = o;
                    }
                }
            }
        }
    }

    // ---- GEMM3: v = u @ Wu^T -> out + Bn*Hn (u staged since prologue) ----
    {
        const int n0 = gid * NCG;
        float* outv = out + (size_t)Bn * Hn;
        gemm_nc<false>(aU, obsg, rot, gid, Wue + (size_t)n0 * Zn, c, tidg); rot++;
#pragma unroll
        for (int mt = 0; mt < 2; mt++) {
            const int r0 = wm * 32 + mt * 16 + t4;
            const int s0 = ss[r0], s1 = ss[r0 + 8];
#pragma unroll
            for (int nt = 0; nt < 4; nt++) {
                const int col = wn * 32 + nt * 8 + t2;
                if (s0 >= 0) {
                    float2 o; o.x = c[mt][nt][0]; o.y = c[mt][nt][1];
                    *(float2*)(outv + (size_t)s0 * Un + n0 + col) = o;
                }
                if (s1 >= 0) {
                    float2 o; o.x = c[mt][nt][2]; o.y = c[mt][nt][3];
                    *(float2*)(outv + (size_t)s1 * Un + n0 + col) = o;
                }
            }
        }
    }
}

// ---------------- launcher ----------------
extern "C" void kernel_launch(void* const* d_in, const int* in_sizes, int n_in,
                              void* d_out, int out_size) {
    (void)in_sizes; (void)n_in; (void)out_size;
    const float* z   = (const float*)d_in[0];
    const float* u   = (const float*)d_in[1];
    const int*   rng = (const int*)d_in[2];
    const float* Wz  = (const float*)d_in[3];
    const float* bz  = (const float*)d_in[4];
    const float* Wh  = (const float*)d_in[5];
    const float* bh  = (const float*)d_in[6];
    const float* Wu  = (const float*)d_in[7];
    float* out = (float*)d_out;

    cudaFuncSetAttribute(k_moe, cudaFuncAttributeMaxDynamicSharedMemorySize, SMEM_DYN);

    k_pre<<<PREBLK + 1, NTPRE>>>(rng, Wz, Wh, Wu, z, u);
    k_moe<<<MAXT, NT, SMEM_DYN>>>(bz, bh, out);
}

// round 14
// speedup vs baseline: 1.0586x; 1.0586x over previous
#include <cuda_runtime.h>
#include <cuda_fp16.h>
#include <cstdint>

#define Bn 8192
#define En 16
#define Zn 256
#define Hn 1024
#define Un 256
#define TM 64
#define MAXT 144
#define NT 512
#define NTPRE 512
#define KC 64
#define LDA 264                    // A smem row stride (halves)
#define TILEB 16384                // one B chunk: 128 rows x 64 halves, swizzled
#define TPE 48                     // tiles per expert: Wz 8, Wh 32, Wu 8

// smem byte offsets
#define OAZ 0                      // z tile / later u tile
#define OA2 33792                  // a tile
#define OBS 67584                  // B rings: group g at OBS + g*3*TILEB
#define SMEM_DYN (OBS + 6*TILEB)   // 165888

// ---------------- device scratch ----------------
__device__ int g_perm[Bn];
__device__ int g_te[MAXT], g_ts[MAXT], g_tr[MAXT];
__device__ int g_ntiles;
__device__ __half g_Wt[(size_t)En * TPE * 8192];   // tiled+swizzled fp16 weights

// ---------------- helpers ----------------
__device__ __forceinline__ uint32_t s2u(const void* p) {
    uint32_t a;
    asm("{ .reg .u64 t; cvta.to.shared.u64 t, %1; cvt.u32.u64 %0, t; }" : "=r"(a) : "l"(p));
    return a;
}
__device__ __forceinline__ void mbar_init(uint32_t a, uint32_t c) {
    asm volatile("mbarrier.init.shared.b64 [%0], %1;" :: "r"(a), "r"(c) : "memory");
}
__device__ __forceinline__ void mbar_expect(uint32_t a, uint32_t bytes) {
    asm volatile("mbarrier.arrive.expect_tx.shared.b64 _, [%0], %1;" :: "r"(a), "r"(bytes) : "memory");
}
__device__ __forceinline__ void bulk_g2s(uint32_t dst, const void* src, uint32_t bytes, uint32_t mbar) {
    asm volatile("cp.async.bulk.shared::cluster.global.mbarrier::complete_tx::bytes [%0], [%1], %2, [%3];"
                 :: "r"(dst), "l"(src), "r"(bytes), "r"(mbar) : "memory");
}
__device__ __forceinline__ void mwait(uint32_t a, uint32_t par) {
    uint32_t done = 0;
    while (!done) {
        asm volatile("{ .reg .pred p; mbarrier.try_wait.parity.acquire.cta.shared::cta.b64 p, [%1], %2; selp.b32 %0, 1, 0, p; }"
                     : "=r"(done) : "r"(a), "r"(par) : "memory");
    }
}
__device__ __forceinline__ void gbar(int id) {
    asm volatile("bar.sync %0, 256;" :: "r"(id) : "memory");
}
__device__ __forceinline__ void ldm4(uint32_t r[4], uint32_t addr) {
    asm volatile("ldmatrix.sync.aligned.m8n8.x4.shared.b16 {%0,%1,%2,%3}, [%4];"
                 : "=r"(r[0]), "=r"(r[1]), "=r"(r[2]), "=r"(r[3]) : "r"(addr));
}
__device__ __forceinline__ void mma16816(float c[4], const uint32_t a[4], uint32_t b0, uint32_t b1) {
    asm volatile("mma.sync.aligned.m16n8k16.row.col.f32.f16.f16.f32 "
                 "{%0,%1,%2,%3}, {%4,%5,%6,%7}, {%8,%9}, {%0,%1,%2,%3};"
                 : "+f"(c[0]), "+f"(c[1]), "+f"(c[2]), "+f"(c[3])
                 : "r"(a[0]), "r"(a[1]), "r"(a[2]), "r"(a[3]), "r"(b0), "r"(b1));
}
// swizzled read offset within a 16KB B tile (128B rows, XOR on 16B units)
__device__ __forceinline__ uint32_t swB(uint32_t r, uint32_t c16) {
    return (r << 7) + (((c16) ^ (r & 7)) << 4);
}

// ---------------- k_pre: setup + weight re-tiling (fp32 -> fp16 swizzled tiles) ----------------
// Total dest units (16B): En*TPE*1024 = 786432; 2 per thread -> 768 blocks.
#define NUNITS (En*TPE*1024)
#define PREBLK (NUNITS/(NTPRE*2))     // 768

__device__ __forceinline__ void cvt_unit(int id, const float* __restrict__ Wz,
                                         const float* __restrict__ Wh,
                                         const float* __restrict__ Wu) {
    const int t = id >> 10;            // tile index
    const int w = id & 1023;           // unit within tile
    const int r = w >> 3, c16s = w & 7;
    const int e = t / TPE, s = t % TPE;
    const float* src; int nc, kc;
    if (s < 8)       { src = Wz + (size_t)e * Zn * Zn; nc = s >> 2;        kc = s & 3; }
    else if (s < 40) { src = Wh + (size_t)e * Hn * Zn; nc = (s - 8) >> 2;  kc = (s - 8) & 3; }
    else             { src = Wu + (size_t)e * Un * Un; nc = (s - 40) >> 2; kc = (s - 40) & 3; }
    const int n = nc * 128 + r;
    const int k = kc * 64 + ((c16s ^ (r & 7)) << 3);
    const float4* sp = (const float4*)(src + (size_t)n * 256 + k);
    const float4 v0 = __ldg(sp), v1 = __ldg(sp + 1);
    union { __half2 h[4]; uint4 q; } P;
    P.h[0] = __floats2half2_rn(v0.x, v0.y);
    P.h[1] = __floats2half2_rn(v0.z, v0.w);
    P.h[2] = __floats2half2_rn(v1.x, v1.y);
    P.h[3] = __floats2half2_rn(v1.z, v1.w);
    *(uint4*)((char*)g_Wt + (size_t)t * TILEB + (uint32_t)((r << 7) + (c16s << 4))) = P.q;
}

__global__ __launch_bounds__(NTPRE) void k_pre(const int* __restrict__ rng,
                                               const float* __restrict__ Wz,
                                               const float* __restrict__ Wh,
                                               const float* __restrict__ Wu) {
    if (blockIdx.x == PREBLK) {
        __shared__ int srng[Bn];
        __shared__ int sc[En], soff[En], scur[En];
        const int tid = threadIdx.x, lane = tid & 31;
        for (int i = tid; i < Bn; i += NTPRE) srng[i] = rng[i];
        if (tid < En) { sc[tid] = 0; scur[tid] = 0; }
        __syncthreads();
        for (int i = tid; i < Bn; i += NTPRE) {
            int e = srng[i];
            unsigned m = __match_any_sync(0xffffffffu, e);
            if (lane == __ffs(m) - 1) atomicAdd(&sc[e], __popc(m));
        }
        __syncthreads();
        if (tid == 0) {
            int acc = 0, nt = 0;
            for (int e = 0; e < En; e++) {
                soff[e] = acc;
                int c = sc[e];
                for (int s = 0; s < c; s += TM) {
                    g_te[nt] = e;
                    g_ts[nt] = acc + s;
                    g_tr[nt] = (c - s) < TM ? (c - s) : TM;
                    nt++;
                }
                acc += c;
            }
            g_ntiles = nt;
        }
        __syncthreads();
        for (int i = tid; i < Bn; i += NTPRE) {
            int e = srng[i];
            unsigned m = __match_any_sync(0xffffffffu, e);
            int leader = __ffs(m) - 1;
            int rank = __popc(m & ((1u << lane) - 1u));
            int base = 0;
            if (lane == leader) base = atomicAdd(&scur[e], __popc(m));
            base = __shfl_sync(0xffffffffu, base, leader);
            g_perm[soff[e] + base + rank] = i;
        }
        return;
    }
    const int base = blockIdx.x * (NTPRE * 2) + threadIdx.x;
    cvt_unit(base, Wz, Wh, Wu);
    cvt_unit(base + NTPRE, Wz, Wh, Wu);
}

// ---------------- A staging: gathered fp32 rows -> fp16 smem (all 512 thr) ----------------
__device__ __forceinline__ void stage_a32(char* smc, int off, const float* __restrict__ g,
                                          const int* ss, int tid) {
#pragma unroll
    for (int i = tid; i < TM * 32; i += NT) {
        int r = i >> 5, c = (i & 31) << 3;
        int s = ss[r];
        uint4 q = make_uint4(0u, 0u, 0u, 0u);
        if (s >= 0) {
            const float4 v0 = __ldg((const float4*)(g + (size_t)s * 256 + c));
            const float4 v1 = __ldg((const float4*)(g + (size_t)s * 256 + c + 4));
            union { __half2 h[4]; uint4 u; } P;
            P.h[0] = __floats2half2_rn(v0.x, v0.y);
            P.h[1] = __floats2half2_rn(v0.z, v0.w);
            P.h[2] = __floats2half2_rn(v1.x, v1.y);
            P.h[3] = __floats2half2_rn(v1.z, v1.w);
            q = P.u;
        }
        *(uint4*)(smc + off + (uint32_t)(r * LDA + c) * 2) = q;
    }
}

// ---------------- group GEMM: one 64x128 output chunk per call ----------------
// B chunks arrive via cp.async.bulk (producer tidg==0) + mbarrier. Global chunk
// counter ck = ck0+kc; buffer = ck%3, parity = (ck/3)&1. Caller prestaged ck0's
// chunk 0 ONLY for the first call (prologue); for later calls the previous call
// staged this call's chunk 0 (gBnext chaining). gbar guards buffer reuse.
__device__ __forceinline__ void gemm_nc(uint32_t aB, uint32_t obsg, uint32_t mb, int gid,
                                        int ck0,
                                        const __half* __restrict__ gB,
                                        const __half* __restrict__ gBnext,
                                        float c[2][4][4], int tidg) {
    const int lane = tidg & 31, wig = tidg >> 5;
    const int wm = wig >> 2, wn = wig & 3;
    const int lrow = (lane & 7) + ((lane >> 3) & 1) * 8;
    const int lk8  = (lane >> 4) * 8;
    const int l16  = lane >> 4;

#pragma unroll
    for (int mt = 0; mt < 2; mt++)
#pragma unroll
        for (int nt = 0; nt < 4; nt++)
#pragma unroll
            for (int j = 0; j < 4; j++) c[mt][nt][j] = 0.f;

#pragma unroll
    for (int kc = 0; kc < 4; kc++) {
        const int ck = ck0 + kc;
        const __half* nsrc = (kc < 3) ? (gB + (size_t)(kc + 1) * 8192) : gBnext;
        if (nsrc && tidg == 0) {
            const uint32_t b1 = (uint32_t)((ck + 1) % 3);
            mbar_expect(mb + b1 * 8, TILEB);
            bulk_g2s(obsg + b1 * TILEB, nsrc, TILEB, mb + b1 * 8);
        }
        mwait(mb + (uint32_t)(ck % 3) * 8, (uint32_t)((ck / 3) & 1));
        gbar(1 + gid);

        const uint32_t bH = obsg + (uint32_t)(ck % 3) * TILEB;
#pragma unroll
        for (int k16 = 0; k16 < 4; k16++) {
            const int ka = kc * KC + k16 * 16 + lk8;
            uint32_t ah[2][4];
#pragma unroll
            for (int mt = 0; mt < 2; mt++)
                ldm4(ah[mt], aB + (uint32_t)((wm * 32 + mt * 16 + lrow) * LDA + ka) * 2);
            uint32_t bf[2][4];
#pragma unroll
            for (int ng = 0; ng < 2; ng++)
                ldm4(bf[ng], bH + swB((uint32_t)(wn * 32 + ng * 16 + lrow),
                                      (uint32_t)(k16 * 2 + l16)));
#pragma unroll
            for (int mt = 0; mt < 2; mt++)
#pragma unroll
                for (int nt = 0; nt < 4; nt++)
                    mma16816(c[mt][nt], ah[mt], bf[nt >> 1][nt & 1], bf[nt >> 1][(nt & 1) + 2]);
        }
    }
}

// ---------------- fused MoE kernel (2 groups, bulk-staged B) ----------------
__global__ __launch_bounds__(NT, 1)
void k_moe(const float* __restrict__ z, const float* __restrict__ u,
           const float* __restrict__ bz, const float* __restrict__ bhb,
           float* __restrict__ out) {
    const int bt = blockIdx.x;
    if (bt >= g_ntiles) return;
    const int e = g_te[bt], start = g_ts[bt], rows = g_tr[bt];
    const int tid = threadIdx.x;
    const int gid = tid >> 8;
    const int tidg = tid & 255;
    const int lane = tid & 31, wig = tidg >> 5;
    const int wm = wig >> 2, wn = wig & 3;
    const int t4 = lane >> 2, t2 = (lane & 3) * 2;

    extern __shared__ char smc[];
    const uint32_t sm0 = s2u(smc);
    const uint32_t aZ = sm0 + OAZ, a2 = sm0 + OA2;
    const uint32_t obsg = sm0 + OBS + (uint32_t)gid * 3 * TILEB;

    __shared__ __align__(8) unsigned long long s_mb[6];
    const uint32_t mb = s2u(s_mb) + (uint32_t)gid * 24;

    __shared__ int ss[TM];
    if (tid < TM) ss[tid] = (tid < rows) ? g_perm[start + tid] : -1;
    if (tid < 6) mbar_init(s2u(s_mb) + tid * 8, 1);
    __syncthreads();

    // per-group tile-base pointers for the 6 gemm calls
    const __half* Wbase = g_Wt + (size_t)e * TPE * 8192;
    const __half* callB[6];
    callB[0] = Wbase + (size_t)(0  + gid * 4) * 8192;                 // GEMM1: Wz nc=gid
#pragma unroll
    for (int j = 0; j < 4; j++)
        callB[1 + j] = Wbase + (size_t)(8 + (j * 2 + gid) * 4) * 8192; // GEMM2: Wh nc=j*2+gid
    callB[5] = Wbase + (size_t)(40 + gid * 4) * 8192;                  // GEMM3: Wu nc=gid

    // prologue: prestage chunk 0 of call 0
    if (tidg == 0) {
        mbar_expect(mb, TILEB);
        bulk_g2s(obsg, callB[0], TILEB, mb);
    }

    stage_a32(smc, OAZ, z, ss, tid);
    __syncthreads();                       // z tile visible

    float c[2][4][4];

    // ---- GEMM1: a = z @ Wz^T + bz -> a2 (fp16); group N-half ----
    {
        const int n0 = gid * 128;
        gemm_nc(aZ, obsg, mb, gid, 0, callB[0], callB[1], c, tidg);
        const float* bzp = bz + (size_t)e * Zn + n0;
#pragma unroll
        for (int mt = 0; mt < 2; mt++) {
            const int r0 = wm * 32 + mt * 16 + t4;
#pragma unroll
            for (int nt = 0; nt < 4; nt++) {
                const int col = wn * 32 + nt * 8 + t2;
                const float2 bb = *(const float2*)(bzp + col);
                uint32_t o = (uint32_t)(r0 * LDA + n0 + col) * 2;
                *(__half2*)(smc + OA2 + o) = __floats2half2_rn(c[mt][nt][0] + bb.x, c[mt][nt][1] + bb.y);
                o = (uint32_t)((r0 + 8) * LDA + n0 + col) * 2;
                *(__half2*)(smc + OA2 + o) = __floats2half2_rn(c[mt][nt][2] + bb.x, c[mt][nt][3] + bb.y);
            }
        }
    }
    __syncthreads();                       // a2 complete; aZ free

    stage_a32(smc, OAZ, u, ss, tid);       // u tile into aZ
    __syncthreads();

    // ---- GEMM2: h = relu(a @ Wh^T + bh) -> out ----
    {
        for (int nc = 0; nc < 4; nc++) {
            const int n0 = nc * 256 + gid * 128;
            gemm_nc(a2, obsg, mb, gid, (1 + nc) * 4, callB[1 + nc], callB[2 + nc], c, tidg);
            const float* bhp = bhb + (size_t)e * Hn + n0;
#pragma unroll
            for (int mt = 0; mt < 2; mt++) {
                const int r0 = wm * 32 + mt * 16 + t4;
                const int s0 = ss[r0], s1 = ss[r0 + 8];
#pragma unroll
                for (int nt = 0; nt < 4; nt++) {
                    const int col = wn * 32 + nt * 8 + t2;
                    const float2 bb = *(const float2*)(bhp + col);
                    if (s0 >= 0) {
                        float2 o;
                        o.x = fmaxf(c[mt][nt][0] + bb.x, 0.f);
                        o.y = fmaxf(c[mt][nt][1] + bb.y, 0.f);
                        *(float2*)(out + (size_t)s0 * Hn + n0 + col) = o;
                    }
                    if (s1 >= 0) {
                        float2 o;
                        o.x = fmaxf(c[mt][nt][2] + bb.x, 0.f);
                        o.y = fmaxf(c[mt][nt][3] + bb.y, 0.f);
                        *(float2*)(out + (size_t)s1 * Hn + n0 + col) = o;
                    }
                }
            }
        }
    }

    // ---- GEMM3: v = u @ Wu^T -> out + Bn*Hn ----
    {
        const int n0 = gid * 128;
        float* outv = out + (size_t)Bn * Hn;
        gemm_nc(aZ, obsg, mb, gid, 20, callB[5], nullptr, c, tidg);
#pragma unroll
        for (int mt = 0; mt < 2; mt++) {
            const int r0 = wm * 32 + mt * 16 + t4;
            const int s0 = ss[r0], s1 = ss[r0 + 8];
#pragma unroll
            for (int nt = 0; nt < 4; nt++) {
                const int col = wn * 32 + nt * 8 + t2;
                if (s0 >= 0) {
                    float2 o; o.x = c[mt][nt][0]; o.y = c[mt][nt][1];
                    *(float2*)(outv + (size_t)s0 * Un + n0 + col) = o;
                }
                if (s1 >= 0) {
                    float2 o; o.x = c[mt][nt][2]; o.y = c[mt][nt][3];
                    *(float2*)(outv + (size_t)s1 * Un + n0 + col) = o;
                }
            }
        }
    }
}

// ---------------- launcher ----------------
extern "C" void kernel_launch(void* const* d_in, const int* in_sizes, int n_in,
                              void* d_out, int out_size) {
    (void)in_sizes; (void)n_in; (void)out_size;
    const float* z   = (const float*)d_in[0];
    const float* u   = (const float*)d_in[1];
    const int*   rng = (const int*)d_in[2];
    const float* Wz  = (const float*)d_in[3];
    const float* bz  = (const float*)d_in[4];
    const float* Wh  = (const float*)d_in[5];
    const float* bh  = (const float*)d_in[6];
    const float* Wu  = (const float*)d_in[7];
    float* out = (float*)d_out;

    cudaFuncSetAttribute(k_moe, cudaFuncAttributeMaxDynamicSharedMemorySize, SMEM_DYN);

    k_pre<<<PREBLK + 1, NTPRE>>>(rng, Wz, Wh, Wu);
    k_moe<<<MAXT, NT, SMEM_DYN>>>(z, u, bz, bh, out);
}